// round 1
// baseline (speedup 1.0000x reference)
#include <cuda_runtime.h>
#include <math.h>

#define HH   8
#define DD   256
#define DKK  32
#define EE   256
#define BBB  16
#define GGG  513
#define NPP  256

#define NORMF 0.17677669529663687f  // 1/sqrt(32)

// ---------------- scratch (static device globals; no allocation) ----------------
__device__ float g_Q[HH * BBB * GGG * DKK];      // main Q projection of q
__device__ float g_K[HH * BBB * GGG * DKK];      // K projection of h (full G)
__device__ float g_V[HH * BBB * GGG * DKK];      // V projection of h (full G)
// g_Qx[0]=Q1(pick diag) [1]=Q2(pick->allpick) [2]=Q3(pick->alldelivery)
// g_Qx[3]=Q4(del diag)  [4]=Q5(del->alldelivery) [5]=Q6(del->allpick)
__device__ float g_Qx[6][HH * BBB * NPP * DKK];
__device__ float g_heads[BBB * GGG * HH * DKK];  // [b][n][h][dk] -> contiguous feature dim

struct ProjParams {
    const float* q;
    const float* h;
    const float* W[9];  // W_query, W_key, W_val, W1..W6
};

// =====================================================================
// Kernel A: projections.  job j, head h:
//   dst[h][gr][k] = sum_d X[b, off+nloc, d] * W[h, d, k]
// block: 128 rows x 32 cols, 256 threads, 4x4 register tile
// =====================================================================
__global__ __launch_bounds__(256) void proj_kernel(ProjParams P) {
    const int job  = blockIdx.z;
    const int head = blockIdx.y;
    const int tile = blockIdx.x;

    int off, cnt;
    if (job <= 2)      { off = 0;        cnt = GGG; }
    else if (job <= 5) { off = 1;        cnt = NPP; }
    else               { off = NPP + 1;  cnt = NPP; }

    const int rows_total = BBB * cnt;
    const int row0 = tile * 128;
    if (row0 >= rows_total) return;

    const float* X = (job == 0) ? P.q : P.h;
    float* dst;
    switch (job) {
        case 0:  dst = g_Q; break;
        case 1:  dst = g_K; break;
        case 2:  dst = g_V; break;
        default: dst = g_Qx[job - 3]; break;
    }
    const float* W = P.W[job] + (size_t)head * DD * DKK;
    dst += (size_t)head * rows_total * DKK;

    __shared__ float Xs[128][33];
    __shared__ float Ws[32][36];

    const int tid = threadIdx.x;
    const int rg  = tid >> 3;   // 0..31 -> rows rg*4..rg*4+3
    const int cg  = tid & 7;    // 0..7  -> cols cg*4..cg*4+3

    float acc[4][4];
#pragma unroll
    for (int i = 0; i < 4; i++)
#pragma unroll
        for (int j = 0; j < 4; j++) acc[i][j] = 0.f;

    for (int dc = 0; dc < DD; dc += 32) {
        // load X chunk: 128 rows x 32 d (1024 float4, 4 per thread)
#pragma unroll
        for (int i = 0; i < 4; i++) {
            int idx = tid + i * 256;          // 0..1023
            int r   = idx >> 3;               // 0..127
            int d4  = idx & 7;                // 0..7
            int gr  = row0 + r;
            int grc = (gr < rows_total) ? gr : 0;
            int b    = grc / cnt;
            int nloc = grc - b * cnt;
            const float4 v = *(const float4*)(X + ((size_t)(b * GGG + off + nloc) * DD + dc + d4 * 4));
            Xs[r][d4 * 4 + 0] = v.x;
            Xs[r][d4 * 4 + 1] = v.y;
            Xs[r][d4 * 4 + 2] = v.z;
            Xs[r][d4 * 4 + 3] = v.w;
        }
        // load W chunk: 32 x 32 (256 float4, 1 per thread)
        {
            int d  = tid >> 3;                // 0..31
            int k4 = tid & 7;                 // 0..7
            const float4 v = *(const float4*)(W + ((size_t)(dc + d) * DKK + k4 * 4));
            Ws[d][k4 * 4 + 0] = v.x;
            Ws[d][k4 * 4 + 1] = v.y;
            Ws[d][k4 * 4 + 2] = v.z;
            Ws[d][k4 * 4 + 3] = v.w;
        }
        __syncthreads();

#pragma unroll
        for (int d = 0; d < 32; d++) {
            float xv[4];
#pragma unroll
            for (int i = 0; i < 4; i++) xv[i] = Xs[rg * 4 + i][d];
            const float4 wv = *(const float4*)&Ws[d][cg * 4];
#pragma unroll
            for (int i = 0; i < 4; i++) {
                acc[i][0] = fmaf(xv[i], wv.x, acc[i][0]);
                acc[i][1] = fmaf(xv[i], wv.y, acc[i][1]);
                acc[i][2] = fmaf(xv[i], wv.z, acc[i][2]);
                acc[i][3] = fmaf(xv[i], wv.w, acc[i][3]);
            }
        }
        __syncthreads();
    }

#pragma unroll
    for (int i = 0; i < 4; i++) {
        int gr = row0 + rg * 4 + i;
        if (gr < rows_total) {
            float4 v = make_float4(acc[i][0], acc[i][1], acc[i][2], acc[i][3]);
            *(float4*)(dst + (size_t)gr * DKK + cg * 4) = v;
        }
    }
}

// =====================================================================
// Kernel B: fused attention with combined-weight online softmax.
// One thread = one query row. block 128 threads, grid (5, B, H).
// =====================================================================
__global__ __launch_bounds__(128) void attn_kernel() {
    const int tile = blockIdx.x;   // 0..4
    const int b    = blockIdx.y;
    const int head = blockIdx.z;
    const int tid  = threadIdx.x;
    const int q    = tile * 128 + tid;
    const bool active = (q < GGG);
    const int hb = head * BBB + b;

    const float* Kbase = g_K + (size_t)hb * GGG * DKK;
    const float* Vbase = g_V + (size_t)hb * GGG * DKK;

    const bool isPick = active && (q >= 1) && (q <= NPP);
    const bool isDel  = active && (q > NPP);
    const bool hasExtra = isPick || isDel;
    const int pd = isPick ? (q - 1) : (isDel ? (q - NPP - 1) : 0);
    const size_t xoff = (size_t)hb * NPP * DKK + (size_t)pd * DKK;

    float qm[DKK], qp[DKK], qd[DKK];
    {
        const float* qptr = g_Q + ((size_t)hb * GGG + (active ? q : 0)) * DKK;
#pragma unroll
        for (int k = 0; k < DKK; k++) qm[k] = NORMF * qptr[k];
    }
    {
        const float* qpSrc = isPick ? (g_Qx[1] + xoff) : (g_Qx[5] + xoff); // Q2 / Q6
        const float* qdSrc = isPick ? (g_Qx[2] + xoff) : (g_Qx[4] + xoff); // Q3 / Q5
#pragma unroll
        for (int k = 0; k < DKK; k++) {
            qp[k] = hasExtra ? NORMF * qpSrc[k] : 0.f;
            qd[k] = hasExtra ? NORMF * qdSrc[k] : 0.f;
        }
    }

    float acc[DKK];
#pragma unroll
    for (int k = 0; k < DKK; k++) acc[k] = 0.f;
    float m = -3.0e38f;
    float l = 0.f;

    __shared__ float Ks[64][DKK];
    __shared__ float Vs[64][DKK];

    for (int t = 0; t < 9; t++) {
        const int nbase  = t * 64;
        const int nvalid = min(64, GGG - nbase);
        // load K/V tile: 512 float4 each, 4 per thread
#pragma unroll
        for (int i = 0; i < 4; i++) {
            int idx = tid + i * 128;      // 0..511
            int n   = idx >> 3;
            int k4  = idx & 7;
            if (n < nvalid) {
                *(float4*)&Ks[n][k4 * 4] = *(const float4*)(Kbase + ((size_t)(nbase + n) * DKK + k4 * 4));
                *(float4*)&Vs[n][k4 * 4] = *(const float4*)(Vbase + ((size_t)(nbase + n) * DKK + k4 * 4));
            }
        }
        __syncthreads();

        if (active) {
            for (int j = 0; j < nvalid; j++) {
                const int n = nbase + j;
                float s1a = 0.f, s1b = 0.f, s1c = 0.f, s1d = 0.f;
                float s2a = 0.f, s2b = 0.f, s2c = 0.f, s2d = 0.f;
                if (n <= NPP) {
#pragma unroll
                    for (int kk = 0; kk < 8; kk++) {
                        const float4 kv = *(const float4*)&Ks[j][kk * 4];
                        s1a = fmaf(qm[kk * 4 + 0], kv.x, s1a);
                        s1b = fmaf(qm[kk * 4 + 1], kv.y, s1b);
                        s1c = fmaf(qm[kk * 4 + 2], kv.z, s1c);
                        s1d = fmaf(qm[kk * 4 + 3], kv.w, s1d);
                        s2a = fmaf(qp[kk * 4 + 0], kv.x, s2a);
                        s2b = fmaf(qp[kk * 4 + 1], kv.y, s2b);
                        s2c = fmaf(qp[kk * 4 + 2], kv.z, s2c);
                        s2d = fmaf(qp[kk * 4 + 3], kv.w, s2d);
                    }
                } else {
#pragma unroll
                    for (int kk = 0; kk < 8; kk++) {
                        const float4 kv = *(const float4*)&Ks[j][kk * 4];
                        s1a = fmaf(qm[kk * 4 + 0], kv.x, s1a);
                        s1b = fmaf(qm[kk * 4 + 1], kv.y, s1b);
                        s1c = fmaf(qm[kk * 4 + 2], kv.z, s1c);
                        s1d = fmaf(qm[kk * 4 + 3], kv.w, s1d);
                        s2a = fmaf(qd[kk * 4 + 0], kv.x, s2a);
                        s2b = fmaf(qd[kk * 4 + 1], kv.y, s2b);
                        s2c = fmaf(qd[kk * 4 + 2], kv.z, s2c);
                        s2d = fmaf(qd[kk * 4 + 3], kv.w, s2d);
                    }
                }
                const float s1 = (s1a + s1b) + (s1c + s1d);
                const float s2 = (s2a + s2b) + (s2c + s2d);
                const bool useExtra = hasExtra && (n != 0);
                const float smax = useExtra ? fmaxf(s1, s2) : s1;
                if (smax > m) {
                    const float c = __expf(m - smax);
                    m = smax;
                    l *= c;
#pragma unroll
                    for (int k = 0; k < DKK; k++) acc[k] *= c;
                }
                float w = __expf(s1 - m);
                if (useExtra) w += __expf(s2 - m);
                l += w;
#pragma unroll
                for (int kk = 0; kk < 8; kk++) {
                    const float4 vv = *(const float4*)&Vs[j][kk * 4];
                    acc[kk * 4 + 0] = fmaf(w, vv.x, acc[kk * 4 + 0]);
                    acc[kk * 4 + 1] = fmaf(w, vv.y, acc[kk * 4 + 1]);
                    acc[kk * 4 + 2] = fmaf(w, vv.z, acc[kk * 4 + 2]);
                    acc[kk * 4 + 3] = fmaf(w, vv.w, acc[kk * 4 + 3]);
                }
            }
        }
        __syncthreads();
    }

    // diagonal extra logit (single key, value shared with that key's V)
    if (hasExtra) {
        const float* qg = isPick ? (g_Qx[0] + xoff) : (g_Qx[3] + xoff); // Q1 / Q4
        const int nd = isPick ? (NPP + q) : (1 + pd);
        const float* kk = Kbase + (size_t)nd * DKK;
        const float* vv = Vbase + (size_t)nd * DKK;
        float s = 0.f;
#pragma unroll
        for (int k = 0; k < DKK; k++) s = fmaf(qg[k], kk[k], s);
        s *= NORMF;
        if (s > m) {
            const float c = __expf(m - s);
            m = s;
            l *= c;
#pragma unroll
            for (int k = 0; k < DKK; k++) acc[k] *= c;
        }
        const float w = __expf(s - m);
        l += w;
#pragma unroll
        for (int k = 0; k < DKK; k++) acc[k] = fmaf(w, vv[k], acc[k]);
    }

    if (active) {
        const float inv = 1.f / l;
        float* dst = g_heads + ((size_t)(b * GGG + q) * HH + head) * DKK;
#pragma unroll
        for (int k = 0; k < DKK; k += 4) {
            float4 v = make_float4(acc[k] * inv, acc[k + 1] * inv, acc[k + 2] * inv, acc[k + 3] * inv);
            *(float4*)(dst + k) = v;
        }
    }
}

// =====================================================================
// Kernel C: out[b*G+n][e] = sum_f heads[b*G+n][f] * Wout_flat[f][e]
// M = B*G = 8208, N = 256, K = 256.  block 64x64, 256 threads, 4x4 tiles.
// =====================================================================
__global__ __launch_bounds__(256) void out_kernel(const float* __restrict__ Wout,
                                                  float* __restrict__ out) {
    const int M = BBB * GGG;
    const int row0 = blockIdx.x * 64;
    const int col0 = blockIdx.y * 64;
    const int tid = threadIdx.x;
    const int rg = tid >> 4;   // 0..15
    const int cg = tid & 15;   // 0..15

    __shared__ float As[64][33];
    __shared__ float Bs[32][64];

    float acc[4][4];
#pragma unroll
    for (int i = 0; i < 4; i++)
#pragma unroll
        for (int j = 0; j < 4; j++) acc[i][j] = 0.f;

    for (int kc = 0; kc < HH * DKK; kc += 32) {
        // A tile: 64x32 (512 float4, 2 per thread)
#pragma unroll
        for (int i = 0; i < 2; i++) {
            int idx = tid + i * 256;
            int r = idx >> 3;
            int d4 = idx & 7;
            int gr = row0 + r;
            int grc = (gr < M) ? gr : 0;
            const float4 v = *(const float4*)(g_heads + (size_t)grc * 256 + kc + d4 * 4);
            As[r][d4 * 4 + 0] = v.x;
            As[r][d4 * 4 + 1] = v.y;
            As[r][d4 * 4 + 2] = v.z;
            As[r][d4 * 4 + 3] = v.w;
        }
        // B tile: 32x64 (512 float4, 2 per thread)
#pragma unroll
        for (int i = 0; i < 2; i++) {
            int idx = tid + i * 256;
            int d = idx >> 4;
            int c4 = idx & 15;
            const float4 v = *(const float4*)(Wout + (size_t)(kc + d) * EE + col0 + c4 * 4);
            *(float4*)&Bs[d][c4 * 4] = v;
        }
        __syncthreads();

#pragma unroll
        for (int d = 0; d < 32; d++) {
            float a[4];
#pragma unroll
            for (int i = 0; i < 4; i++) a[i] = As[rg * 4 + i][d];
            const float4 b4 = *(const float4*)&Bs[d][cg * 4];
#pragma unroll
            for (int i = 0; i < 4; i++) {
                acc[i][0] = fmaf(a[i], b4.x, acc[i][0]);
                acc[i][1] = fmaf(a[i], b4.y, acc[i][1]);
                acc[i][2] = fmaf(a[i], b4.z, acc[i][2]);
                acc[i][3] = fmaf(a[i], b4.w, acc[i][3]);
            }
        }
        __syncthreads();
    }

#pragma unroll
    for (int i = 0; i < 4; i++) {
        int gr = row0 + rg * 4 + i;
        if (gr < M) {
            float4 v = make_float4(acc[i][0], acc[i][1], acc[i][2], acc[i][3]);
            *(float4*)(out + (size_t)gr * EE + col0 + cg * 4) = v;
        }
    }
}

// =====================================================================
extern "C" void kernel_launch(void* const* d_in, const int* in_sizes, int n_in,
                              void* d_out, int out_size) {
    ProjParams P;
    P.q = (const float*)d_in[0];
    P.h = (const float*)d_in[1];
    for (int i = 0; i < 9; i++) P.W[i] = (const float*)d_in[2 + i];
    const float* Wout = (const float*)d_in[11];
    float* out = (float*)d_out;

    dim3 gA(65, HH, 9);
    proj_kernel<<<gA, 256>>>(P);

    dim3 gB(5, BBB, HH);
    attn_kernel<<<gB, 128>>>();

    dim3 gC((BBB * GGG + 63) / 64, EE / 64);
    out_kernel<<<gC, 256>>>(Wout, out);
}

// round 2
// speedup vs baseline: 1.0130x; 1.0130x over previous
#include <cuda_runtime.h>
#include <math.h>

#define HH   8
#define DD   256
#define DKK  32
#define EE   256
#define BBB  16
#define GGG  513
#define NPP  256

#define NORMF 0.17677669529663687f  // 1/sqrt(32)

// ---------------- scratch (static device globals; no allocation) ----------------
__device__ float g_Q[HH * BBB * GGG * DKK];
__device__ float g_K[HH * BBB * GGG * DKK];
__device__ float g_V[HH * BBB * GGG * DKK];
// g_Qx[0]=Q1(pick diag) [1]=Q2(pick->allpick) [2]=Q3(pick->alldelivery)
// g_Qx[3]=Q4(del diag)  [4]=Q5(del->alldelivery) [5]=Q6(del->allpick)
__device__ float g_Qx[6][HH * BBB * NPP * DKK];
__device__ float g_heads[BBB * GGG * HH * DKK];  // [b][n][h][dk]

__device__ __forceinline__ float* dst_of(int i) {
    switch (i) {
        case 0:  return g_Q;
        case 1:  return g_K;
        case 2:  return g_V;
        default: return g_Qx[i - 3];
    }
}

// =====================================================================
// Kernel A: projections, NW weights sharing the same X rows.
//   dst[w][head][gr][k] = sum_d X[b, off+nloc, d] * W[w][head, d, k]
// block: 128 rows x 32 cols x NW weights, 256 threads, 4x4 reg tile per weight.
// Xs stored transposed: Xs[d][r] so x-operand reads are LDS.128.
// =====================================================================
template <int NW>
__global__ __launch_bounds__(256) void proj_kernel(
        const float* __restrict__ X,
        const float* __restrict__ Wa, const float* __restrict__ Wb, const float* __restrict__ Wc,
        int off, int cnt, int da, int db, int dc_idx) {
    const int head = blockIdx.y;
    const int tile = blockIdx.x;

    const int rows_total = BBB * cnt;
    const int row0 = tile * 128;
    if (row0 >= rows_total) return;

    const float* Wsrc[NW];
    float* Dp[NW];
    {
        const float* wlist[3] = {Wa, Wb, Wc};
        const int    dlist[3] = {da, db, dc_idx};
#pragma unroll
        for (int w = 0; w < NW; w++) {
            Wsrc[w] = wlist[w] + (size_t)head * DD * DKK;
            Dp[w]   = dst_of(dlist[w]) + (size_t)head * rows_total * DKK;
        }
    }

    __shared__ float Xs[32][132];        // [d][row], padded
    __shared__ float Ws[NW][32][36];     // [w][d][k]

    const int tid = threadIdx.x;
    const int rg  = tid >> 3;   // 0..31 -> rows rg*4..+3
    const int cg  = tid & 7;    // 0..7  -> cols cg*4..+3

    float acc[NW][4][4];
#pragma unroll
    for (int w = 0; w < NW; w++)
#pragma unroll
        for (int i = 0; i < 4; i++)
#pragma unroll
            for (int j = 0; j < 4; j++) acc[w][i][j] = 0.f;

    for (int dc = 0; dc < DD; dc += 32) {
        // X chunk: 128 rows x 32 d, stored transposed. 1024 float4, 4/thread.
        // idx: d4 = idx>>7 (0..7), r = idx&127 -> smem stores row-contiguous (no conflicts)
#pragma unroll
        for (int i = 0; i < 4; i++) {
            int idx = tid + i * 256;
            int d4  = idx >> 7;
            int r   = idx & 127;
            int gr  = row0 + r;
            int grc = (gr < rows_total) ? gr : 0;
            int b    = grc / cnt;
            int nloc = grc - b * cnt;
            const float4 v = *(const float4*)(X + ((size_t)(b * GGG + off + nloc) * DD + dc + d4 * 4));
            Xs[d4 * 4 + 0][r] = v.x;
            Xs[d4 * 4 + 1][r] = v.y;
            Xs[d4 * 4 + 2][r] = v.z;
            Xs[d4 * 4 + 3][r] = v.w;
        }
        // W chunks: NW x 32 x 32 (256 float4 each, 1/thread per weight)
        {
            int d  = tid >> 3;
            int k4 = tid & 7;
#pragma unroll
            for (int w = 0; w < NW; w++) {
                const float4 v = *(const float4*)(Wsrc[w] + ((size_t)(dc + d) * DKK + k4 * 4));
                Ws[w][d][k4 * 4 + 0] = v.x;
                Ws[w][d][k4 * 4 + 1] = v.y;
                Ws[w][d][k4 * 4 + 2] = v.z;
                Ws[w][d][k4 * 4 + 3] = v.w;
            }
        }
        __syncthreads();

#pragma unroll 8
        for (int d = 0; d < 32; d++) {
            const float4 xv = *(const float4*)&Xs[d][rg * 4];
#pragma unroll
            for (int w = 0; w < NW; w++) {
                const float4 wv = *(const float4*)&Ws[w][d][cg * 4];
                acc[w][0][0] = fmaf(xv.x, wv.x, acc[w][0][0]);
                acc[w][0][1] = fmaf(xv.x, wv.y, acc[w][0][1]);
                acc[w][0][2] = fmaf(xv.x, wv.z, acc[w][0][2]);
                acc[w][0][3] = fmaf(xv.x, wv.w, acc[w][0][3]);
                acc[w][1][0] = fmaf(xv.y, wv.x, acc[w][1][0]);
                acc[w][1][1] = fmaf(xv.y, wv.y, acc[w][1][1]);
                acc[w][1][2] = fmaf(xv.y, wv.z, acc[w][1][2]);
                acc[w][1][3] = fmaf(xv.y, wv.w, acc[w][1][3]);
                acc[w][2][0] = fmaf(xv.z, wv.x, acc[w][2][0]);
                acc[w][2][1] = fmaf(xv.z, wv.y, acc[w][2][1]);
                acc[w][2][2] = fmaf(xv.z, wv.z, acc[w][2][2]);
                acc[w][2][3] = fmaf(xv.z, wv.w, acc[w][2][3]);
                acc[w][3][0] = fmaf(xv.w, wv.x, acc[w][3][0]);
                acc[w][3][1] = fmaf(xv.w, wv.y, acc[w][3][1]);
                acc[w][3][2] = fmaf(xv.w, wv.z, acc[w][3][2]);
                acc[w][3][3] = fmaf(xv.w, wv.w, acc[w][3][3]);
            }
        }
        __syncthreads();
    }

#pragma unroll
    for (int w = 0; w < NW; w++)
#pragma unroll
        for (int i = 0; i < 4; i++) {
            int gr = row0 + rg * 4 + i;
            if (gr < rows_total) {
                float4 v = make_float4(acc[w][i][0], acc[w][i][1], acc[w][i][2], acc[w][i][3]);
                *(float4*)(Dp[w] + (size_t)gr * DKK + cg * 4) = v;
            }
        }
}

// =====================================================================
// Kernel B: fused attention, combined-weight online softmax.
// One thread = one query row. block 192 threads, grid (3, B, H).
// Key ranges are contiguous -> two phases (pick keys 1..256, delivery 257..512)
// with a single extra-query register set reloaded per phase. Key 0 up front.
// =====================================================================
__global__ __launch_bounds__(192) void attn_kernel() {
    const int b    = blockIdx.y;
    const int head = blockIdx.z;
    const int tid  = threadIdx.x;
    const int q    = blockIdx.x * 192 + tid;
    const bool active = (q < GGG);
    const int hb = head * BBB + b;

    const float* Kbase = g_K + (size_t)hb * GGG * DKK;
    const float* Vbase = g_V + (size_t)hb * GGG * DKK;

    const bool isPick = active && (q >= 1) && (q <= NPP);
    const bool isDel  = active && (q > NPP);
    const bool hasExtra = isPick || isDel;
    const int pd = isPick ? (q - 1) : (isDel ? (q - NPP - 1) : 0);
    const size_t xoff = (size_t)hb * NPP * DKK + (size_t)pd * DKK;

    float qm[DKK];
    {
        const float* qptr = g_Q + ((size_t)hb * GGG + (active ? q : 0)) * DKK;
#pragma unroll
        for (int k = 0; k < DKK; k++) qm[k] = NORMF * qptr[k];
    }

    float acc[DKK];
    float m, l;
    // ---- key 0 (main query only) ----
    {
        float sa = 0.f, sb = 0.f, sc = 0.f, sd = 0.f;
#pragma unroll
        for (int kk = 0; kk < 8; kk++) {
            const float4 kv = *(const float4*)(Kbase + kk * 4);
            sa = fmaf(qm[kk * 4 + 0], kv.x, sa);
            sb = fmaf(qm[kk * 4 + 1], kv.y, sb);
            sc = fmaf(qm[kk * 4 + 2], kv.z, sc);
            sd = fmaf(qm[kk * 4 + 3], kv.w, sd);
        }
        m = (sa + sb) + (sc + sd);
        l = 1.f;
#pragma unroll
        for (int kk = 0; kk < 8; kk++) {
            const float4 vv = *(const float4*)(Vbase + kk * 4);
            acc[kk * 4 + 0] = vv.x;
            acc[kk * 4 + 1] = vv.y;
            acc[kk * 4 + 2] = vv.z;
            acc[kk * 4 + 3] = vv.w;
        }
    }

    __shared__ float Ks[64][DKK];
    __shared__ float Vs[64][DKK];

    float qe[DKK];

#pragma unroll 1
    for (int phase = 0; phase < 2; phase++) {
        // extra query for this key range
        {
            const float* qeSrc = (phase == 0)
                ? (isPick ? (g_Qx[1] + xoff) : (g_Qx[5] + xoff))   // Q2 / Q6 on pick keys
                : (isPick ? (g_Qx[2] + xoff) : (g_Qx[4] + xoff));  // Q3 / Q5 on delivery keys
#pragma unroll
            for (int k = 0; k < DKK; k++) qe[k] = NORMF * qeSrc[k];
        }
        const float* Kp = Kbase + (size_t)(1 + phase * NPP) * DKK;
        const float* Vp = Vbase + (size_t)(1 + phase * NPP) * DKK;

#pragma unroll 1
        for (int t = 0; t < 4; t++) {
            __syncthreads();
            // load 64 keys/values: 512 float4 each
            for (int idx = tid; idx < 512; idx += 192) {
                int n  = idx >> 3;
                int k4 = idx & 7;
                *(float4*)&Ks[n][k4 * 4] = *(const float4*)(Kp + ((size_t)(t * 64 + n) * DKK + k4 * 4));
                *(float4*)&Vs[n][k4 * 4] = *(const float4*)(Vp + ((size_t)(t * 64 + n) * DKK + k4 * 4));
            }
            __syncthreads();

            if (active) {
#pragma unroll 2
                for (int j = 0; j < 64; j++) {
                    float s1a = 0.f, s1b = 0.f, s1c = 0.f, s1d = 0.f;
                    float s2a = 0.f, s2b = 0.f, s2c = 0.f, s2d = 0.f;
#pragma unroll
                    for (int kk = 0; kk < 8; kk++) {
                        const float4 kv = *(const float4*)&Ks[j][kk * 4];
                        s1a = fmaf(qm[kk * 4 + 0], kv.x, s1a);
                        s1b = fmaf(qm[kk * 4 + 1], kv.y, s1b);
                        s1c = fmaf(qm[kk * 4 + 2], kv.z, s1c);
                        s1d = fmaf(qm[kk * 4 + 3], kv.w, s1d);
                        s2a = fmaf(qe[kk * 4 + 0], kv.x, s2a);
                        s2b = fmaf(qe[kk * 4 + 1], kv.y, s2b);
                        s2c = fmaf(qe[kk * 4 + 2], kv.z, s2c);
                        s2d = fmaf(qe[kk * 4 + 3], kv.w, s2d);
                    }
                    const float s1 = (s1a + s1b) + (s1c + s1d);
                    const float s2 = (s2a + s2b) + (s2c + s2d);
                    const float smax = hasExtra ? fmaxf(s1, s2) : s1;
                    if (smax > m) {
                        const float c = __expf(m - smax);
                        m = smax;
                        l *= c;
#pragma unroll
                        for (int k = 0; k < DKK; k++) acc[k] *= c;
                    }
                    float w = __expf(s1 - m);
                    if (hasExtra) w += __expf(s2 - m);
                    l += w;
#pragma unroll
                    for (int kk = 0; kk < 8; kk++) {
                        const float4 vv = *(const float4*)&Vs[j][kk * 4];
                        acc[kk * 4 + 0] = fmaf(w, vv.x, acc[kk * 4 + 0]);
                        acc[kk * 4 + 1] = fmaf(w, vv.y, acc[kk * 4 + 1]);
                        acc[kk * 4 + 2] = fmaf(w, vv.z, acc[kk * 4 + 2]);
                        acc[kk * 4 + 3] = fmaf(w, vv.w, acc[kk * 4 + 3]);
                    }
                }
            }
        }
    }

    // ---- diagonal extra logit (single key) ----
    if (hasExtra) {
        const float* qg = isPick ? (g_Qx[0] + xoff) : (g_Qx[3] + xoff); // Q1 / Q4
        const int nd = isPick ? (NPP + q) : (1 + pd);
        const float* kk = Kbase + (size_t)nd * DKK;
        const float* vv = Vbase + (size_t)nd * DKK;
        float s = 0.f;
#pragma unroll
        for (int k = 0; k < DKK; k++) s = fmaf(qg[k], kk[k], s);
        s *= NORMF;
        if (s > m) {
            const float c = __expf(m - s);
            m = s;
            l *= c;
#pragma unroll
            for (int k = 0; k < DKK; k++) acc[k] *= c;
        }
        const float w = __expf(s - m);
        l += w;
#pragma unroll
        for (int k = 0; k < DKK; k++) acc[k] = fmaf(w, vv[k], acc[k]);
    }

    if (active) {
        const float inv = 1.f / l;
        float* dst = g_heads + ((size_t)(b * GGG + q) * HH + head) * DKK;
#pragma unroll
        for (int k = 0; k < DKK; k += 4) {
            float4 v = make_float4(acc[k] * inv, acc[k + 1] * inv, acc[k + 2] * inv, acc[k + 3] * inv);
            *(float4*)(dst + k) = v;
        }
    }
}

// =====================================================================
// Kernel C: out = heads(8208x256) @ Wout(256x256). 64x64 tiles, 4x4/thread.
// =====================================================================
__global__ __launch_bounds__(256) void out_kernel(const float* __restrict__ Wout,
                                                  float* __restrict__ out) {
    const int M = BBB * GGG;
    const int row0 = blockIdx.x * 64;
    const int col0 = blockIdx.y * 64;
    const int tid = threadIdx.x;
    const int rg = tid >> 4;
    const int cg = tid & 15;

    __shared__ float As[64][33];
    __shared__ float Bs[32][64];

    float acc[4][4];
#pragma unroll
    for (int i = 0; i < 4; i++)
#pragma unroll
        for (int j = 0; j < 4; j++) acc[i][j] = 0.f;

    for (int kc = 0; kc < HH * DKK; kc += 32) {
#pragma unroll
        for (int i = 0; i < 2; i++) {
            int idx = tid + i * 256;
            int r = idx >> 3;
            int d4 = idx & 7;
            int gr = row0 + r;
            int grc = (gr < M) ? gr : 0;
            const float4 v = *(const float4*)(g_heads + (size_t)grc * 256 + kc + d4 * 4);
            As[r][d4 * 4 + 0] = v.x;
            As[r][d4 * 4 + 1] = v.y;
            As[r][d4 * 4 + 2] = v.z;
            As[r][d4 * 4 + 3] = v.w;
        }
#pragma unroll
        for (int i = 0; i < 2; i++) {
            int idx = tid + i * 256;
            int d = idx >> 4;
            int c4 = idx & 15;
            const float4 v = *(const float4*)(Wout + (size_t)(kc + d) * EE + col0 + c4 * 4);
            *(float4*)&Bs[d][c4 * 4] = v;
        }
        __syncthreads();

#pragma unroll
        for (int d = 0; d < 32; d++) {
            float a[4];
#pragma unroll
            for (int i = 0; i < 4; i++) a[i] = As[rg * 4 + i][d];
            const float4 b4 = *(const float4*)&Bs[d][cg * 4];
#pragma unroll
            for (int i = 0; i < 4; i++) {
                acc[i][0] = fmaf(a[i], b4.x, acc[i][0]);
                acc[i][1] = fmaf(a[i], b4.y, acc[i][1]);
                acc[i][2] = fmaf(a[i], b4.z, acc[i][2]);
                acc[i][3] = fmaf(a[i], b4.w, acc[i][3]);
            }
        }
        __syncthreads();
    }

#pragma unroll
    for (int i = 0; i < 4; i++) {
        int gr = row0 + rg * 4 + i;
        if (gr < M) {
            float4 v = make_float4(acc[i][0], acc[i][1], acc[i][2], acc[i][3]);
            *(float4*)(out + (size_t)gr * EE + col0 + cg * 4) = v;
        }
    }
}

// =====================================================================
extern "C" void kernel_launch(void* const* d_in, const int* in_sizes, int n_in,
                              void* d_out, int out_size) {
    const float* q = (const float*)d_in[0];
    const float* h = (const float*)d_in[1];
    const float* Wq  = (const float*)d_in[2];
    const float* Wk  = (const float*)d_in[3];
    const float* Wv  = (const float*)d_in[4];
    const float* W1  = (const float*)d_in[5];
    const float* W2  = (const float*)d_in[6];
    const float* W3  = (const float*)d_in[7];
    const float* W4  = (const float*)d_in[8];
    const float* W5  = (const float*)d_in[9];
    const float* W6  = (const float*)d_in[10];
    const float* Wout = (const float*)d_in[11];
    float* out = (float*)d_out;

    // group 0: Q projection of q (full G rows)
    proj_kernel<1><<<dim3(65, HH), 256>>>(q, Wq, Wq, Wq, 0, GGG, 0, 0, 0);
    // group 1: K,V projections of h (full G rows)
    proj_kernel<2><<<dim3(65, HH), 256>>>(h, Wk, Wv, Wv, 0, GGG, 1, 2, 2);
    // group 2: W1,W2,W3 on pick rows
    proj_kernel<3><<<dim3(32, HH), 256>>>(h, W1, W2, W3, 1, NPP, 3, 4, 5);
    // group 3: W4,W5,W6 on delivery rows
    proj_kernel<3><<<dim3(32, HH), 256>>>(h, W4, W5, W6, NPP + 1, NPP, 6, 7, 8);

    attn_kernel<<<dim3(3, BBB, HH), 192>>>();

    out_kernel<<<dim3((BBB * GGG + 63) / 64, EE / 64), 256>>>(Wout, out);
}

// round 4
// speedup vs baseline: 1.3308x; 1.3137x over previous
#include <cuda_runtime.h>
#include <cuda_bf16.h>
#include <cstdint>
#include <math.h>

#define HH   8
#define DD   256
#define DKK  32
#define EE   256
#define BBB  16
#define GGG  513
#define NPP  256

#define NORMF 0.17677669529663687f  // 1/sqrt(32)

// ---------------- scratch (static device globals; no allocation) ----------------
__device__ float g_Q[HH * BBB * GGG * DKK];
__device__ float g_K[HH * BBB * GGG * DKK];
__device__ float g_V[HH * BBB * GGG * DKK];
// g_Qx[0]=Q1(pick diag) [1]=Q2(pick->allpick) [2]=Q3(pick->alldelivery)
// g_Qx[3]=Q4(del diag)  [4]=Q5(del->alldelivery) [5]=Q6(del->allpick)
__device__ float g_Qx[6][HH * BBB * NPP * DKK];
__device__ float g_heads[BBB * GGG * HH * DKK];  // [b][n][h][dk]

// bf16 hi/lo splits of inputs and (transposed) weights
#define XELEMS (BBB * GGG * DD)          // 2101248
__device__ __nv_bfloat16 g_qhi[XELEMS];
__device__ __nv_bfloat16 g_qlo[XELEMS];
__device__ __nv_bfloat16 g_hhi[XELEMS];
__device__ __nv_bfloat16 g_hlo[XELEMS];
// W^T: [job][head][k_out=32][d=256]
#define WTELEMS (9 * HH * DKK * DD)      // 589824
__device__ __nv_bfloat16 g_Wthi[WTELEMS];
__device__ __nv_bfloat16 g_Wtlo[WTELEMS];

__device__ __forceinline__ float* dst_of(int i) {
    switch (i) {
        case 0:  return g_Q;
        case 1:  return g_K;
        case 2:  return g_V;
        default: return g_Qx[i - 3];
    }
}

__device__ __forceinline__ uint32_t smem_u32(const void* p) {
    uint32_t a;
    asm("{ .reg .u64 t; cvta.to.shared.u64 t, %1; cvt.u32.u64 %0, t; }" : "=r"(a) : "l"(p));
    return a;
}

#define LDMX4(r, addr) \
    asm volatile("ldmatrix.sync.aligned.m8n8.x4.shared.b16 {%0,%1,%2,%3}, [%4];" \
        : "=r"((r)[0]), "=r"((r)[1]), "=r"((r)[2]), "=r"((r)[3]) : "r"(addr))
#define LDMX2(r, addr) \
    asm volatile("ldmatrix.sync.aligned.m8n8.x2.shared.b16 {%0,%1}, [%2];" \
        : "=r"((r)[0]), "=r"((r)[1]) : "r"(addr))

#define MMA16816(c, a, b) \
    asm volatile("mma.sync.aligned.m16n8k16.row.col.f32.bf16.bf16.f32 " \
        "{%0,%1,%2,%3}, {%4,%5,%6,%7}, {%8,%9}, {%0,%1,%2,%3};" \
        : "+f"((c)[0]), "+f"((c)[1]), "+f"((c)[2]), "+f"((c)[3]) \
        : "r"((a)[0]), "r"((a)[1]), "r"((a)[2]), "r"((a)[3]), "r"((b)[0]), "r"((b)[1]))

// =====================================================================
// Prep 1: fp32 -> bf16 hi/lo split of q and h.  8 elems per thread.
// =====================================================================
__global__ __launch_bounds__(256) void cvt_x_kernel(const float* __restrict__ q,
                                                    const float* __restrict__ h) {
    const int which = blockIdx.y;
    const float* src = which ? h : q;
    __nv_bfloat16* dhi = which ? g_hhi : g_qhi;
    __nv_bfloat16* dlo = which ? g_hlo : g_qlo;

    int t = blockIdx.x * 256 + threadIdx.x;
    if (t * 8 >= XELEMS) return;
    const float4 v0 = ((const float4*)src)[t * 2];
    const float4 v1 = ((const float4*)src)[t * 2 + 1];
    float xs[8] = {v0.x, v0.y, v0.z, v0.w, v1.x, v1.y, v1.z, v1.w};
    __nv_bfloat162 hp[4], lp[4];
#pragma unroll
    for (int i = 0; i < 4; i++) {
        __nv_bfloat16 h0 = __float2bfloat16(xs[2 * i]);
        __nv_bfloat16 h1 = __float2bfloat16(xs[2 * i + 1]);
        __nv_bfloat16 l0 = __float2bfloat16(xs[2 * i] - __bfloat162float(h0));
        __nv_bfloat16 l1 = __float2bfloat16(xs[2 * i + 1] - __bfloat162float(h1));
        hp[i] = __halves2bfloat162(h0, h1);
        lp[i] = __halves2bfloat162(l0, l1);
    }
    ((uint4*)dhi)[t] = *(uint4*)hp;
    ((uint4*)dlo)[t] = *(uint4*)lp;
}

// =====================================================================
// Prep 2: W[j][h][d][k] fp32 -> W^T hi/lo bf16 [j][h][k][d]
// =====================================================================
struct WPtrs { const float* w[9]; };

__global__ __launch_bounds__(256) void cvt_w_kernel(WPtrs P) {
    int idx = blockIdx.x * 256 + threadIdx.x;
    if (idx >= WTELEMS) return;
    int j = idx >> 16;
    int h = (idx >> 13) & 7;
    int k = (idx >> 8) & 31;
    int d = idx & 255;
    float x = P.w[j][(size_t)h * DD * DKK + (size_t)d * DKK + k];
    __nv_bfloat16 hi = __float2bfloat16(x);
    __nv_bfloat16 lo = __float2bfloat16(x - __bfloat162float(hi));
    g_Wthi[idx] = hi;
    g_Wtlo[idx] = lo;
}

// =====================================================================
// Kernel A (HMMA): proj tile per block: job, head, 128 rows x 32 cols.
//   D = Xhi@Whi^T + Xlo@Whi^T + Xhi@Wlo^T   (fp32 accumulate)
// K=256 in 4 smem chunks of 64; per chunk 4 k16-steps.
// 8 warps; warp w -> rows w*16..w*16+15, all 32 cols (4 n-frags).
// =====================================================================
#define XS_STRIDE 72   // bf16 elems per row (64 + 8 pad); 144B, 16B-aligned

__global__ __launch_bounds__(256) void proj_hmma_kernel() {
    const int job  = blockIdx.z;
    const int head = blockIdx.y;
    const int tile = blockIdx.x;

    const int off = (job < 3) ? 0 : ((job < 6) ? 1 : (NPP + 1));
    const int cnt = (job < 3) ? GGG : NPP;
    const int rows_total = BBB * cnt;
    const int row0 = tile * 128;
    if (row0 >= rows_total) return;

    const __nv_bfloat16* Xhi = (job == 0) ? g_qhi : g_hhi;
    const __nv_bfloat16* Xlo = (job == 0) ? g_qlo : g_hlo;
    const __nv_bfloat16* Whi = g_Wthi + ((size_t)(job * HH + head)) * (DKK * DD);
    const __nv_bfloat16* Wlo = g_Wtlo + ((size_t)(job * HH + head)) * (DKK * DD);
    float* dst = dst_of(job) + (size_t)head * rows_total * DKK;

    __shared__ __nv_bfloat16 Xs[2][128][XS_STRIDE];
    __shared__ __nv_bfloat16 Ws[2][32][XS_STRIDE];

    const int tid  = threadIdx.x;
    const int warp = tid >> 5;
    const int lane = tid & 31;
    const int g    = lane >> 2;   // 0..7
    const int tig  = lane & 3;    // 0..3

    float acc[4][4];
#pragma unroll
    for (int nf = 0; nf < 4; nf++)
#pragma unroll
        for (int i = 0; i < 4; i++) acc[nf][i] = 0.f;

    // ldmatrix base addresses (bytes), fixed per thread; add ks*32 per k16-step
    const int rowA  = warp * 16 + (lane & 7) + ((lane >> 3) & 1) * 8;
    const int colA0 = ((lane >> 4) & 1) * 8;
    const uint32_t addrAhi0 = smem_u32(&Xs[0][rowA][colA0]);
    const uint32_t addrAlo0 = smem_u32(&Xs[1][rowA][colA0]);
    const int rowB  = lane & 7;
    const int colB0 = ((lane & 15) >> 3) * 8;
    uint32_t addrBhi0[4], addrBlo0[4];
#pragma unroll
    for (int nf = 0; nf < 4; nf++) {
        addrBhi0[nf] = smem_u32(&Ws[0][nf * 8 + rowB][colB0]);
        addrBlo0[nf] = smem_u32(&Ws[1][nf * 8 + rowB][colB0]);
    }

#pragma unroll 1
    for (int c = 0; c < 4; c++) {
        const int dc = c * 64;
        __syncthreads();
        // ---- fill Xs hi/lo: 128 rows x 64 elems ----
#pragma unroll
        for (int i = 0; i < 4; i++) {
            int idx = tid + i * 256;          // 0..1023
            int row = idx >> 3;
            int v   = idx & 7;                // 8 bf16 = 16B
            int gr  = row0 + row;
            int grc = (gr < rows_total) ? gr : (rows_total - 1);
            int b    = grc / cnt;
            int nloc = grc - b * cnt;
            size_t gix = ((size_t)(b * GGG + off + nloc)) * DD + dc + v * 8;
            *(uint4*)&Xs[0][row][v * 8] = *(const uint4*)(Xhi + gix);
            *(uint4*)&Xs[1][row][v * 8] = *(const uint4*)(Xlo + gix);
        }
        // ---- fill Ws hi/lo: 32 rows x 64 elems ----
        {
            int row = tid >> 3;               // 0..31
            int v   = tid & 7;
            size_t gix = (size_t)row * DD + dc + v * 8;
            *(uint4*)&Ws[0][row][v * 8] = *(const uint4*)(Whi + gix);
            *(uint4*)&Ws[1][row][v * 8] = *(const uint4*)(Wlo + gix);
        }
        __syncthreads();

#pragma unroll
        for (int ks = 0; ks < 4; ks++) {
            const uint32_t kadd = ks * 32;    // 16 bf16 = 32 bytes
            uint32_t ahi[4], alo[4];
            LDMX4(ahi, addrAhi0 + kadd);
            LDMX4(alo, addrAlo0 + kadd);
#pragma unroll
            for (int nf = 0; nf < 4; nf++) {
                uint32_t bh[2], bl[2];
                LDMX2(bh, addrBhi0[nf] + kadd);
                LDMX2(bl, addrBlo0[nf] + kadd);
                MMA16816(acc[nf], ahi, bh);
                MMA16816(acc[nf], alo, bh);
                MMA16816(acc[nf], ahi, bl);
            }
        }
    }

    // ---- epilogue: C frag (row g / g+8, col tig*2..+1 per n-frag) ----
    const int r0 = row0 + warp * 16 + g;
    const int r1 = r0 + 8;
#pragma unroll
    for (int nf = 0; nf < 4; nf++) {
        const int col = nf * 8 + tig * 2;
        if (r0 < rows_total) {
            float2 v = make_float2(acc[nf][0], acc[nf][1]);
            *(float2*)(dst + (size_t)r0 * DKK + col) = v;
        }
        if (r1 < rows_total) {
            float2 v = make_float2(acc[nf][2], acc[nf][3]);
            *(float2*)(dst + (size_t)r1 * DKK + col) = v;
        }
    }
}

// =====================================================================
// Kernel B: fused attention (unchanged, passing version)
// =====================================================================
__global__ __launch_bounds__(192) void attn_kernel() {
    const int b    = blockIdx.y;
    const int head = blockIdx.z;
    const int tid  = threadIdx.x;
    const int q    = blockIdx.x * 192 + tid;
    const bool active = (q < GGG);
    const int hb = head * BBB + b;

    const float* Kbase = g_K + (size_t)hb * GGG * DKK;
    const float* Vbase = g_V + (size_t)hb * GGG * DKK;

    const bool isPick = active && (q >= 1) && (q <= NPP);
    const bool isDel  = active && (q > NPP);
    const bool hasExtra = isPick || isDel;
    const int pd = isPick ? (q - 1) : (isDel ? (q - NPP - 1) : 0);
    const size_t xoff = (size_t)hb * NPP * DKK + (size_t)pd * DKK;

    float qm[DKK];
    {
        const float* qptr = g_Q + ((size_t)hb * GGG + (active ? q : 0)) * DKK;
#pragma unroll
        for (int k = 0; k < DKK; k++) qm[k] = NORMF * qptr[k];
    }

    float acc[DKK];
    float m, l;
    {
        float sa = 0.f, sb = 0.f, sc = 0.f, sd = 0.f;
#pragma unroll
        for (int kk = 0; kk < 8; kk++) {
            const float4 kv = *(const float4*)(Kbase + kk * 4);
            sa = fmaf(qm[kk * 4 + 0], kv.x, sa);
            sb = fmaf(qm[kk * 4 + 1], kv.y, sb);
            sc = fmaf(qm[kk * 4 + 2], kv.z, sc);
            sd = fmaf(qm[kk * 4 + 3], kv.w, sd);
        }
        m = (sa + sb) + (sc + sd);
        l = 1.f;
#pragma unroll
        for (int kk = 0; kk < 8; kk++) {
            const float4 vv = *(const float4*)(Vbase + kk * 4);
            acc[kk * 4 + 0] = vv.x;
            acc[kk * 4 + 1] = vv.y;
            acc[kk * 4 + 2] = vv.z;
            acc[kk * 4 + 3] = vv.w;
        }
    }

    __shared__ float Ks[64][DKK];
    __shared__ float Vs[64][DKK];

    float qe[DKK];

#pragma unroll 1
    for (int phase = 0; phase < 2; phase++) {
        {
            const float* qeSrc = (phase == 0)
                ? (isPick ? (g_Qx[1] + xoff) : (g_Qx[5] + xoff))
                : (isPick ? (g_Qx[2] + xoff) : (g_Qx[4] + xoff));
#pragma unroll
            for (int k = 0; k < DKK; k++) qe[k] = NORMF * qeSrc[k];
        }
        const float* Kp = Kbase + (size_t)(1 + phase * NPP) * DKK;
        const float* Vp = Vbase + (size_t)(1 + phase * NPP) * DKK;

#pragma unroll 1
        for (int t = 0; t < 4; t++) {
            __syncthreads();
            for (int idx = tid; idx < 512; idx += 192) {
                int n  = idx >> 3;
                int k4 = idx & 7;
                *(float4*)&Ks[n][k4 * 4] = *(const float4*)(Kp + ((size_t)(t * 64 + n) * DKK + k4 * 4));
                *(float4*)&Vs[n][k4 * 4] = *(const float4*)(Vp + ((size_t)(t * 64 + n) * DKK + k4 * 4));
            }
            __syncthreads();

            if (active) {
#pragma unroll 2
                for (int j = 0; j < 64; j++) {
                    float s1a = 0.f, s1b = 0.f, s1c = 0.f, s1d = 0.f;
                    float s2a = 0.f, s2b = 0.f, s2c = 0.f, s2d = 0.f;
#pragma unroll
                    for (int kk = 0; kk < 8; kk++) {
                        const float4 kv = *(const float4*)&Ks[j][kk * 4];
                        s1a = fmaf(qm[kk * 4 + 0], kv.x, s1a);
                        s1b = fmaf(qm[kk * 4 + 1], kv.y, s1b);
                        s1c = fmaf(qm[kk * 4 + 2], kv.z, s1c);
                        s1d = fmaf(qm[kk * 4 + 3], kv.w, s1d);
                        s2a = fmaf(qe[kk * 4 + 0], kv.x, s2a);
                        s2b = fmaf(qe[kk * 4 + 1], kv.y, s2b);
                        s2c = fmaf(qe[kk * 4 + 2], kv.z, s2c);
                        s2d = fmaf(qe[kk * 4 + 3], kv.w, s2d);
                    }
                    const float s1 = (s1a + s1b) + (s1c + s1d);
                    const float s2 = (s2a + s2b) + (s2c + s2d);
                    const float smax = hasExtra ? fmaxf(s1, s2) : s1;
                    if (smax > m) {
                        const float c = __expf(m - smax);
                        m = smax;
                        l *= c;
#pragma unroll
                        for (int k = 0; k < DKK; k++) acc[k] *= c;
                    }
                    float w = __expf(s1 - m);
                    if (hasExtra) w += __expf(s2 - m);
                    l += w;
#pragma unroll
                    for (int kk = 0; kk < 8; kk++) {
                        const float4 vv = *(const float4*)&Vs[j][kk * 4];
                        acc[kk * 4 + 0] = fmaf(w, vv.x, acc[kk * 4 + 0]);
                        acc[kk * 4 + 1] = fmaf(w, vv.y, acc[kk * 4 + 1]);
                        acc[kk * 4 + 2] = fmaf(w, vv.z, acc[kk * 4 + 2]);
                        acc[kk * 4 + 3] = fmaf(w, vv.w, acc[kk * 4 + 3]);
                    }
                }
            }
        }
    }

    if (hasExtra) {
        const float* qg = isPick ? (g_Qx[0] + xoff) : (g_Qx[3] + xoff);
        const int nd = isPick ? (NPP + q) : (1 + pd);
        const float* kk = Kbase + (size_t)nd * DKK;
        const float* vv = Vbase + (size_t)nd * DKK;
        float s = 0.f;
#pragma unroll
        for (int k = 0; k < DKK; k++) s = fmaf(qg[k], kk[k], s);
        s *= NORMF;
        if (s > m) {
            const float c = __expf(m - s);
            m = s;
            l *= c;
#pragma unroll
            for (int k = 0; k < DKK; k++) acc[k] *= c;
        }
        const float w = __expf(s - m);
        l += w;
#pragma unroll
        for (int k = 0; k < DKK; k++) acc[k] = fmaf(w, vv[k], acc[k]);
    }

    if (active) {
        const float inv = 1.f / l;
        float* dst = g_heads + ((size_t)(b * GGG + q) * HH + head) * DKK;
#pragma unroll
        for (int k = 0; k < DKK; k += 4) {
            float4 v = make_float4(acc[k] * inv, acc[k + 1] * inv, acc[k + 2] * inv, acc[k + 3] * inv);
            *(float4*)(dst + k) = v;
        }
    }
}

// =====================================================================
// Kernel C: out = heads(8208x256) @ Wout(256x256). (unchanged)
// =====================================================================
__global__ __launch_bounds__(256) void out_kernel(const float* __restrict__ Wout,
                                                  float* __restrict__ out) {
    const int M = BBB * GGG;
    const int row0 = blockIdx.x * 64;
    const int col0 = blockIdx.y * 64;
    const int tid = threadIdx.x;
    const int rg = tid >> 4;
    const int cg = tid & 15;

    __shared__ float As[64][33];
    __shared__ float Bs[32][64];

    float acc[4][4];
#pragma unroll
    for (int i = 0; i < 4; i++)
#pragma unroll
        for (int j = 0; j < 4; j++) acc[i][j] = 0.f;

    for (int kc = 0; kc < HH * DKK; kc += 32) {
#pragma unroll
        for (int i = 0; i < 2; i++) {
            int idx = tid + i * 256;
            int r = idx >> 3;
            int d4 = idx & 7;
            int gr = row0 + r;
            int grc = (gr < M) ? gr : 0;
            const float4 v = *(const float4*)(g_heads + (size_t)grc * 256 + kc + d4 * 4);
            As[r][d4 * 4 + 0] = v.x;
            As[r][d4 * 4 + 1] = v.y;
            As[r][d4 * 4 + 2] = v.z;
            As[r][d4 * 4 + 3] = v.w;
        }
#pragma unroll
        for (int i = 0; i < 2; i++) {
            int idx = tid + i * 256;
            int d = idx >> 4;
            int c4 = idx & 15;
            const float4 v = *(const float4*)(Wout + (size_t)(kc + d) * EE + col0 + c4 * 4);
            *(float4*)&Bs[d][c4 * 4] = v;
        }
        __syncthreads();

#pragma unroll
        for (int d = 0; d < 32; d++) {
            float a[4];
#pragma unroll
            for (int i = 0; i < 4; i++) a[i] = As[rg * 4 + i][d];
            const float4 b4 = *(const float4*)&Bs[d][cg * 4];
#pragma unroll
            for (int i = 0; i < 4; i++) {
                acc[i][0] = fmaf(a[i], b4.x, acc[i][0]);
                acc[i][1] = fmaf(a[i], b4.y, acc[i][1]);
                acc[i][2] = fmaf(a[i], b4.z, acc[i][2]);
                acc[i][3] = fmaf(a[i], b4.w, acc[i][3]);
            }
        }
        __syncthreads();
    }

#pragma unroll
    for (int i = 0; i < 4; i++) {
        int gr = row0 + rg * 4 + i;
        if (gr < M) {
            float4 v = make_float4(acc[i][0], acc[i][1], acc[i][2], acc[i][3]);
            *(float4*)(out + (size_t)gr * EE + col0 + cg * 4) = v;
        }
    }
}

// =====================================================================
extern "C" void kernel_launch(void* const* d_in, const int* in_sizes, int n_in,
                              void* d_out, int out_size) {
    const float* q = (const float*)d_in[0];
    const float* h = (const float*)d_in[1];
    WPtrs WP;
    for (int i = 0; i < 9; i++) WP.w[i] = (const float*)d_in[2 + i];
    const float* Wout = (const float*)d_in[11];
    float* out = (float*)d_out;

    // prep: bf16 hi/lo splits
    cvt_x_kernel<<<dim3((XELEMS / 8 + 255) / 256, 2), 256>>>(q, h);
    cvt_w_kernel<<<(WTELEMS + 255) / 256, 256>>>(WP);

    // HMMA projections (all 9 jobs x 8 heads)
    proj_hmma_kernel<<<dim3(65, HH, 9), 256>>>();

    attn_kernel<<<dim3(3, BBB, HH), 192>>>();

    out_kernel<<<dim3((BBB * GGG + 63) / 64, EE / 64), 256>>>(Wout, out);
}

// round 6
// speedup vs baseline: 2.2747x; 1.7093x over previous
#include <cuda_runtime.h>
#include <cuda_bf16.h>
#include <cstdint>
#include <math.h>

#define HH   8
#define DD   256
#define DKK  32
#define EE   256
#define BBB  16
#define GGG  513
#define NPP  256
#define NKEY 512

#define NORMF 0.17677669529663687f  // 1/sqrt(32)

// ---------------- scratch (static device globals; no allocation) ----------------
__device__ float g_Q[HH * BBB * GGG * DKK];
__device__ float g_K[HH * BBB * GGG * DKK];
__device__ float g_V[HH * BBB * GGG * DKK];
// g_Qx[0]=Q1(pick diag) [1]=Q2(pick->allpick) [2]=Q3(pick->alldelivery)
// g_Qx[3]=Q4(del diag)  [4]=Q5(del->alldelivery) [5]=Q6(del->allpick)
__device__ float g_Qx[6][HH * BBB * NPP * DKK];
__device__ float g_heads[BBB * GGG * HH * DKK];  // [b][n][h][dk]

// bf16 hi/lo splits of inputs and (transposed) weights
#define XELEMS (BBB * GGG * DD)          // 2101248
__device__ __nv_bfloat16 g_qhi[XELEMS];
__device__ __nv_bfloat16 g_qlo[XELEMS];
__device__ __nv_bfloat16 g_hhi[XELEMS];
__device__ __nv_bfloat16 g_hlo[XELEMS];
// W^T: [job][head][k_out=32][d=256]
#define WTELEMS (9 * HH * DKK * DD)      // 589824
__device__ __nv_bfloat16 g_Wthi[WTELEMS];
__device__ __nv_bfloat16 g_Wtlo[WTELEMS];

// bf16 K (keys 1..512) and transposed V for attention MMA
__device__ __nv_bfloat16 g_Kbh[HH * BBB * NKEY * DKK];
__device__ __nv_bfloat16 g_Kbl[HH * BBB * NKEY * DKK];
__device__ __nv_bfloat16 g_Vtbh[HH * BBB * DKK * NKEY];
__device__ __nv_bfloat16 g_Vtbl[HH * BBB * DKK * NKEY];

__device__ __forceinline__ float* dst_of(int i) {
    switch (i) {
        case 0:  return g_Q;
        case 1:  return g_K;
        case 2:  return g_V;
        default: return g_Qx[i - 3];
    }
}

__device__ __forceinline__ uint32_t smem_u32(const void* p) {
    uint32_t a;
    asm("{ .reg .u64 t; cvta.to.shared.u64 t, %1; cvt.u32.u64 %0, t; }" : "=r"(a) : "l"(p));
    return a;
}

#define LDMX4(r, addr) \
    asm volatile("ldmatrix.sync.aligned.m8n8.x4.shared.b16 {%0,%1,%2,%3}, [%4];" \
        : "=r"((r)[0]), "=r"((r)[1]), "=r"((r)[2]), "=r"((r)[3]) : "r"(addr))
#define LDMX2(r, addr) \
    asm volatile("ldmatrix.sync.aligned.m8n8.x2.shared.b16 {%0,%1}, [%2];" \
        : "=r"((r)[0]), "=r"((r)[1]) : "r"(addr))

#define MMA16816(c, a, b) \
    asm volatile("mma.sync.aligned.m16n8k16.row.col.f32.bf16.bf16.f32 " \
        "{%0,%1,%2,%3}, {%4,%5,%6,%7}, {%8,%9}, {%0,%1,%2,%3};" \
        : "+f"((c)[0]), "+f"((c)[1]), "+f"((c)[2]), "+f"((c)[3]) \
        : "r"((a)[0]), "r"((a)[1]), "r"((a)[2]), "r"((a)[3]), "r"((b)[0]), "r"((b)[1]))

__device__ __forceinline__ void split2(float a, float b, uint32_t& hi, uint32_t& lo) {
    __nv_bfloat16 ha = __float2bfloat16(a), hb = __float2bfloat16(b);
    __nv_bfloat162 hh = __halves2bfloat162(ha, hb);
    __nv_bfloat162 ll = __halves2bfloat162(__float2bfloat16(a - __bfloat162float(ha)),
                                           __float2bfloat16(b - __bfloat162float(hb)));
    hi = *(uint32_t*)&hh;
    lo = *(uint32_t*)&ll;
}

// =====================================================================
// Prep 1: fp32 -> bf16 hi/lo split of q and h.
// =====================================================================
__global__ __launch_bounds__(256) void cvt_x_kernel(const float* __restrict__ q,
                                                    const float* __restrict__ h) {
    const int which = blockIdx.y;
    const float* src = which ? h : q;
    __nv_bfloat16* dhi = which ? g_hhi : g_qhi;
    __nv_bfloat16* dlo = which ? g_hlo : g_qlo;

    int t = blockIdx.x * 256 + threadIdx.x;
    if (t * 8 >= XELEMS) return;
    const float4 v0 = ((const float4*)src)[t * 2];
    const float4 v1 = ((const float4*)src)[t * 2 + 1];
    float xs[8] = {v0.x, v0.y, v0.z, v0.w, v1.x, v1.y, v1.z, v1.w};
    __nv_bfloat162 hp[4], lp[4];
#pragma unroll
    for (int i = 0; i < 4; i++) {
        __nv_bfloat16 h0 = __float2bfloat16(xs[2 * i]);
        __nv_bfloat16 h1 = __float2bfloat16(xs[2 * i + 1]);
        __nv_bfloat16 l0 = __float2bfloat16(xs[2 * i] - __bfloat162float(h0));
        __nv_bfloat16 l1 = __float2bfloat16(xs[2 * i + 1] - __bfloat162float(h1));
        hp[i] = __halves2bfloat162(h0, h1);
        lp[i] = __halves2bfloat162(l0, l1);
    }
    ((uint4*)dhi)[t] = *(uint4*)hp;
    ((uint4*)dlo)[t] = *(uint4*)lp;
}

// =====================================================================
// Prep 2: W[j][h][d][k] fp32 -> W^T hi/lo bf16 [j][h][k][d]
// =====================================================================
struct WPtrs { const float* w[9]; };

__global__ __launch_bounds__(256) void cvt_w_kernel(WPtrs P) {
    int idx = blockIdx.x * 256 + threadIdx.x;
    if (idx >= WTELEMS) return;
    int j = idx >> 16;
    int h = (idx >> 13) & 7;
    int k = (idx >> 8) & 31;
    int d = idx & 255;
    float x = P.w[j][(size_t)h * DD * DKK + (size_t)d * DKK + k];
    __nv_bfloat16 hi = __float2bfloat16(x);
    __nv_bfloat16 lo = __float2bfloat16(x - __bfloat162float(hi));
    g_Wthi[idx] = hi;
    g_Wtlo[idx] = lo;
}

// =====================================================================
// Kernel A (HMMA): projections (unchanged, proven)
// =====================================================================
#define XS_STRIDE 72

__global__ __launch_bounds__(256) void proj_hmma_kernel() {
    const int job  = blockIdx.z;
    const int head = blockIdx.y;
    const int tile = blockIdx.x;

    const int off = (job < 3) ? 0 : ((job < 6) ? 1 : (NPP + 1));
    const int cnt = (job < 3) ? GGG : NPP;
    const int rows_total = BBB * cnt;
    const int row0 = tile * 128;
    if (row0 >= rows_total) return;

    const __nv_bfloat16* Xhi = (job == 0) ? g_qhi : g_hhi;
    const __nv_bfloat16* Xlo = (job == 0) ? g_qlo : g_hlo;
    const __nv_bfloat16* Whi = g_Wthi + ((size_t)(job * HH + head)) * (DKK * DD);
    const __nv_bfloat16* Wlo = g_Wtlo + ((size_t)(job * HH + head)) * (DKK * DD);
    float* dst = dst_of(job) + (size_t)head * rows_total * DKK;

    __shared__ __nv_bfloat16 Xs[2][128][XS_STRIDE];
    __shared__ __nv_bfloat16 Ws[2][32][XS_STRIDE];

    const int tid  = threadIdx.x;
    const int warp = tid >> 5;
    const int lane = tid & 31;
    const int g    = lane >> 2;
    const int tig  = lane & 3;

    float acc[4][4];
#pragma unroll
    for (int nf = 0; nf < 4; nf++)
#pragma unroll
        for (int i = 0; i < 4; i++) acc[nf][i] = 0.f;

    const int rowA  = warp * 16 + (lane & 7) + ((lane >> 3) & 1) * 8;
    const int colA0 = ((lane >> 4) & 1) * 8;
    const uint32_t addrAhi0 = smem_u32(&Xs[0][rowA][colA0]);
    const uint32_t addrAlo0 = smem_u32(&Xs[1][rowA][colA0]);
    const int rowB  = lane & 7;
    const int colB0 = ((lane >> 3) & 1) * 8;
    uint32_t addrBhi0[4], addrBlo0[4];
#pragma unroll
    for (int nf = 0; nf < 4; nf++) {
        addrBhi0[nf] = smem_u32(&Ws[0][nf * 8 + rowB][colB0]);
        addrBlo0[nf] = smem_u32(&Ws[1][nf * 8 + rowB][colB0]);
    }

#pragma unroll 1
    for (int c = 0; c < 4; c++) {
        const int dc = c * 64;
        __syncthreads();
#pragma unroll
        for (int i = 0; i < 4; i++) {
            int idx = tid + i * 256;
            int row = idx >> 3;
            int v   = idx & 7;
            int gr  = row0 + row;
            int grc = (gr < rows_total) ? gr : (rows_total - 1);
            int b    = grc / cnt;
            int nloc = grc - b * cnt;
            size_t gix = ((size_t)(b * GGG + off + nloc)) * DD + dc + v * 8;
            *(uint4*)&Xs[0][row][v * 8] = *(const uint4*)(Xhi + gix);
            *(uint4*)&Xs[1][row][v * 8] = *(const uint4*)(Xlo + gix);
        }
        {
            int row = tid >> 3;
            int v   = tid & 7;
            size_t gix = (size_t)row * DD + dc + v * 8;
            *(uint4*)&Ws[0][row][v * 8] = *(const uint4*)(Whi + gix);
            *(uint4*)&Ws[1][row][v * 8] = *(const uint4*)(Wlo + gix);
        }
        __syncthreads();

#pragma unroll
        for (int ks = 0; ks < 4; ks++) {
            const uint32_t kadd = ks * 32;
            uint32_t ahi[4], alo[4];
            LDMX4(ahi, addrAhi0 + kadd);
            LDMX4(alo, addrAlo0 + kadd);
#pragma unroll
            for (int nf = 0; nf < 4; nf++) {
                uint32_t bh[2], bl[2];
                LDMX2(bh, addrBhi0[nf] + kadd);
                LDMX2(bl, addrBlo0[nf] + kadd);
                MMA16816(acc[nf], ahi, bh);
                MMA16816(acc[nf], alo, bh);
                MMA16816(acc[nf], ahi, bl);
            }
        }
    }

    const int r0 = row0 + warp * 16 + g;
    const int r1 = r0 + 8;
#pragma unroll
    for (int nf = 0; nf < 4; nf++) {
        const int col = nf * 8 + tig * 2;
        if (r0 < rows_total) {
            float2 v = make_float2(acc[nf][0], acc[nf][1]);
            *(float2*)(dst + (size_t)r0 * DKK + col) = v;
        }
        if (r1 < rows_total) {
            float2 v = make_float2(acc[nf][2], acc[nf][3]);
            *(float2*)(dst + (size_t)r1 * DKK + col) = v;
        }
    }
}

// =====================================================================
// Prep 3: K,V fp32 -> bf16 hi/lo; V transposed per hb.
// grid (8 ktiles, 128 hb), 256 threads.
// =====================================================================
__global__ __launch_bounds__(256) void cvt_kv_kernel() {
    const int kt = blockIdx.x;
    const int hb = blockIdx.y;
    const int tid = threadIdx.x;
    __shared__ float vs[64][33];

#pragma unroll
    for (int i = 0; i < 8; i++) {
        int idx = tid + i * 256;
        int key = idx >> 5;
        int dk  = idx & 31;
        size_t gsrc = ((size_t)hb * GGG + 1 + kt * 64 + key) * DKK + dk;
        float kv = g_K[gsrc];
        __nv_bfloat16 kh = __float2bfloat16(kv);
        size_t kd = ((size_t)hb * NKEY + kt * 64 + key) * DKK + dk;
        g_Kbh[kd] = kh;
        g_Kbl[kd] = __float2bfloat16(kv - __bfloat162float(kh));
        vs[key][dk] = g_V[gsrc];
    }
    __syncthreads();
#pragma unroll
    for (int i = 0; i < 8; i++) {
        int idx = tid + i * 256;
        int d = idx >> 6;
        int j = idx & 63;
        float vv = vs[j][d];
        __nv_bfloat16 vh = __float2bfloat16(vv);
        size_t o = ((size_t)hb * DKK + d) * NKEY + kt * 64 + j;
        g_Vtbh[o] = vh;
        g_Vtbl[o] = __float2bfloat16(vv - __bfloat162float(vh));
    }
}

// =====================================================================
// Kernel B (HMMA flash attention).
// Block: 256 thr (8 warps), 128-query tile of one (head,b).
// Keys 1..512 in 8 tiles of 64 (0-3 pick, 4-7 delivery); key 0 + diagonal scalar.
// =====================================================================
#define STQ 40
#define STK 40
#define STV 72
#define O_QMHI 0
#define O_QMLO 10240
#define O_EPHI 20480
#define O_EPLO 30720
#define O_EDHI 40960
#define O_EDLO 51200
#define O_KHI  61440
#define O_KLO  66560
#define O_VTHI 71680
#define O_VTLO 76288
#define SMEM_ATTN 80896

__global__ __launch_bounds__(256) void attn_hmma_kernel() {
    extern __shared__ char sm[];
    const int qbase = blockIdx.x * 128;
    const int b     = blockIdx.y;
    const int head  = blockIdx.z;
    const int hb    = head * BBB + b;
    const int tid   = threadIdx.x;
    const int warp  = tid >> 5;
    const int lane  = tid & 31;
    const int g     = lane >> 2;
    const int tig   = lane & 3;

    __nv_bfloat16* sQmHi = (__nv_bfloat16*)(sm + O_QMHI);
    __nv_bfloat16* sQmLo = (__nv_bfloat16*)(sm + O_QMLO);
    __nv_bfloat16* sEpHi = (__nv_bfloat16*)(sm + O_EPHI);
    __nv_bfloat16* sEpLo = (__nv_bfloat16*)(sm + O_EPLO);
    __nv_bfloat16* sEdHi = (__nv_bfloat16*)(sm + O_EDHI);
    __nv_bfloat16* sEdLo = (__nv_bfloat16*)(sm + O_EDLO);
    __nv_bfloat16* sKhi  = (__nv_bfloat16*)(sm + O_KHI);
    __nv_bfloat16* sKlo  = (__nv_bfloat16*)(sm + O_KLO);
    __nv_bfloat16* sVhi  = (__nv_bfloat16*)(sm + O_VTHI);
    __nv_bfloat16* sVlo  = (__nv_bfloat16*)(sm + O_VTLO);

    // ---- prologue: convert queries into smem (scaled, hi/lo) ----
    for (int idx = tid; idx < 1024; idx += 256) {
        int row = idx >> 3, c4 = idx & 7;
        int qq = qbase + row;
        int qc = (qq < GGG) ? qq : (GGG - 1);
        const int so = row * STQ + c4 * 4;
        {
            const float4 v = *(const float4*)(g_Q + ((size_t)hb * GGG + qc) * DKK + c4 * 4);
            uint32_t h0, l0, h1, l1;
            split2(v.x * NORMF, v.y * NORMF, h0, l0);
            split2(v.z * NORMF, v.w * NORMF, h1, l1);
            *(uint2*)(sQmHi + so) = make_uint2(h0, h1);
            *(uint2*)(sQmLo + so) = make_uint2(l0, l1);
        }
        if (qc == 0) {
            *(uint2*)(sEpHi + so) = make_uint2(0, 0);
            *(uint2*)(sEpLo + so) = make_uint2(0, 0);
            *(uint2*)(sEdHi + so) = make_uint2(0, 0);
            *(uint2*)(sEdLo + so) = make_uint2(0, 0);
        } else {
            bool pick = (qc <= NPP);
            int ppd = pick ? (qc - 1) : (qc - NPP - 1);
            size_t xo = ((size_t)hb * NPP + ppd) * DKK + c4 * 4;
            const float4 ve = *(const float4*)((pick ? g_Qx[1] : g_Qx[5]) + xo);
            const float4 vd = *(const float4*)((pick ? g_Qx[2] : g_Qx[4]) + xo);
            uint32_t h0, l0, h1, l1;
            split2(ve.x * NORMF, ve.y * NORMF, h0, l0);
            split2(ve.z * NORMF, ve.w * NORMF, h1, l1);
            *(uint2*)(sEpHi + so) = make_uint2(h0, h1);
            *(uint2*)(sEpLo + so) = make_uint2(l0, l1);
            split2(vd.x * NORMF, vd.y * NORMF, h0, l0);
            split2(vd.z * NORMF, vd.w * NORMF, h1, l1);
            *(uint2*)(sEdHi + so) = make_uint2(h0, h1);
            *(uint2*)(sEdLo + so) = make_uint2(l0, l1);
        }
    }

    // ---- init from key 0 (main query only) ----
    const int r0g = qbase + warp * 16 + g;      // row for r=0
    const int r1g = r0g + 8;
    float m0, m1, l0, l1;
    float acc[4][4];
    {
        const float* K0 = g_K + (size_t)hb * GGG * DKK;
        const float* V0 = g_V + (size_t)hb * GGG * DKK;
        int rc0 = (r0g < GGG) ? r0g : (GGG - 1);
        int rc1 = (r1g < GGG) ? r1g : (GGG - 1);
        const float* q0 = g_Q + ((size_t)hb * GGG + rc0) * DKK;
        const float* q1 = g_Q + ((size_t)hb * GGG + rc1) * DKK;
        float s0 = 0.f, s1 = 0.f;
#pragma unroll
        for (int k = 0; k < DKK; k++) {
            float kk = K0[k];
            s0 = fmaf(q0[k], kk, s0);
            s1 = fmaf(q1[k], kk, s1);
        }
        m0 = s0 * NORMF;
        m1 = s1 * NORMF;
        l0 = (tig == 0) ? 1.f : 0.f;
        l1 = l0;
#pragma unroll
        for (int vf = 0; vf < 4; vf++) {
            float va = V0[vf * 8 + 2 * tig];
            float vb = V0[vf * 8 + 2 * tig + 1];
            acc[vf][0] = va; acc[vf][1] = vb;
            acc[vf][2] = va; acc[vf][3] = vb;
        }
    }

    // ldmatrix addresses
    const int rowA  = warp * 16 + (lane & 7) + ((lane >> 3) & 1) * 8;
    const int colA0 = ((lane >> 4) & 1) * 8;
    const uint32_t aoff = (uint32_t)(rowA * STQ + colA0) * 2;
    const uint32_t sbase = smem_u32(sm);
    const uint32_t aQmHi = sbase + O_QMHI + aoff;
    const uint32_t aQmLo = sbase + O_QMLO + aoff;
    const uint32_t aEpHi = sbase + O_EPHI + aoff;
    const uint32_t aEpLo = sbase + O_EPLO + aoff;
    const uint32_t aEdHi = sbase + O_EDHI + aoff;
    const uint32_t aEdLo = sbase + O_EDLO + aoff;
    const int rowB  = lane & 7;
    const int colB0 = ((lane >> 3) & 1) * 8;

    const bool extra0 = (r0g != 0);   // only global row 0 lacks the extra logit

#pragma unroll 1
    for (int t = 0; t < 8; t++) {
        __syncthreads();
        // load K tile (64 keys x 32 dk) and Vt tile (32 dk x 64 keys), hi/lo
        for (int idx = tid; idx < 512; idx += 256) {
            {
                int row = idx >> 3, c4 = idx & 7;
                size_t gsrc = ((size_t)hb * NKEY + t * 64 + row) * DKK + c4 * 4;
                *(uint2*)(sKhi + row * STK + c4 * 4) = *(const uint2*)(g_Kbh + gsrc);
                *(uint2*)(sKlo + row * STK + c4 * 4) = *(const uint2*)(g_Kbl + gsrc);
            }
            {
                int row = idx >> 4, c4 = idx & 15;
                size_t gsrc = ((size_t)hb * DKK + row) * NKEY + t * 64 + c4 * 4;
                *(uint2*)(sVhi + row * STV + c4 * 4) = *(const uint2*)(g_Vtbh + gsrc);
                *(uint2*)(sVlo + row * STV + c4 * 4) = *(const uint2*)(g_Vtbl + gsrc);
            }
        }
        __syncthreads();

        const uint32_t aEHi = (t < 4) ? aEpHi : aEdHi;
        const uint32_t aELo = (t < 4) ? aEpLo : aEdLo;

        float S1[8][4], S2[8][4];
#pragma unroll
        for (int nf = 0; nf < 8; nf++)
#pragma unroll
            for (int j = 0; j < 4; j++) { S1[nf][j] = 0.f; S2[nf][j] = 0.f; }

#pragma unroll
        for (int ks = 0; ks < 2; ks++) {
            uint32_t am[4], al[4], ae[4], af[4];
            LDMX4(am, aQmHi + ks * 32);
            LDMX4(al, aQmLo + ks * 32);
            LDMX4(ae, aEHi + ks * 32);
            LDMX4(af, aELo + ks * 32);
#pragma unroll
            for (int nf = 0; nf < 8; nf++) {
                uint32_t kboff = (uint32_t)((nf * 8 + rowB) * STK + colB0) * 2 + ks * 32;
                uint32_t kh[2], kl[2];
                LDMX2(kh, sbase + O_KHI + kboff);
                LDMX2(kl, sbase + O_KLO + kboff);
                MMA16816(S1[nf], am, kh);
                MMA16816(S1[nf], al, kh);
                MMA16816(S1[nf], am, kl);
                MMA16816(S2[nf], ae, kh);
                MMA16816(S2[nf], af, kh);
                MMA16816(S2[nf], ae, kl);
            }
        }

        // ---- online softmax (combined weight) ----
        float mx0 = -3.0e38f, mx1 = -3.0e38f;
#pragma unroll
        for (int nf = 0; nf < 8; nf++) {
            mx0 = fmaxf(mx0, fmaxf(S1[nf][0], S1[nf][1]));
            mx1 = fmaxf(mx1, fmaxf(S1[nf][2], S1[nf][3]));
            if (extra0) mx0 = fmaxf(mx0, fmaxf(S2[nf][0], S2[nf][1]));
            mx1 = fmaxf(mx1, fmaxf(S2[nf][2], S2[nf][3]));
        }
        mx0 = fmaxf(mx0, __shfl_xor_sync(0xffffffffu, mx0, 1));
        mx0 = fmaxf(mx0, __shfl_xor_sync(0xffffffffu, mx0, 2));
        mx1 = fmaxf(mx1, __shfl_xor_sync(0xffffffffu, mx1, 1));
        mx1 = fmaxf(mx1, __shfl_xor_sync(0xffffffffu, mx1, 2));

        float mn0 = fmaxf(m0, mx0), mn1 = fmaxf(m1, mx1);
        float c0 = __expf(m0 - mn0), c1 = __expf(m1 - mn1);
        m0 = mn0; m1 = mn1;
        l0 *= c0; l1 *= c1;
#pragma unroll
        for (int vf = 0; vf < 4; vf++) {
            acc[vf][0] *= c0; acc[vf][1] *= c0;
            acc[vf][2] *= c1; acc[vf][3] *= c1;
        }
#pragma unroll
        for (int nf = 0; nf < 8; nf++) {
            float w0 = __expf(S1[nf][0] - m0);
            float w1 = __expf(S1[nf][1] - m0);
            float w2 = __expf(S1[nf][2] - m1);
            float w3 = __expf(S1[nf][3] - m1);
            if (extra0) {
                w0 += __expf(S2[nf][0] - m0);
                w1 += __expf(S2[nf][1] - m0);
            }
            w2 += __expf(S2[nf][2] - m1);
            w3 += __expf(S2[nf][3] - m1);
            l0 += w0 + w1; l1 += w2 + w3;
            S1[nf][0] = w0; S1[nf][1] = w1; S1[nf][2] = w2; S1[nf][3] = w3;
        }

        // ---- P @ V ----
#pragma unroll
        for (int ks = 0; ks < 4; ks++) {
            uint32_t ph[4], pl[4];
            split2(S1[2 * ks][0], S1[2 * ks][1], ph[0], pl[0]);
            split2(S1[2 * ks][2], S1[2 * ks][3], ph[1], pl[1]);
            split2(S1[2 * ks + 1][0], S1[2 * ks + 1][1], ph[2], pl[2]);
            split2(S1[2 * ks + 1][2], S1[2 * ks + 1][3], ph[3], pl[3]);
#pragma unroll
            for (int vf = 0; vf < 4; vf++) {
                uint32_t vboff = (uint32_t)((vf * 8 + rowB) * STV + ks * 16 + colB0) * 2;
                uint32_t vh[2], vl[2];
                LDMX2(vh, sbase + O_VTHI + vboff);
                LDMX2(vl, sbase + O_VTLO + vboff);
                MMA16816(acc[vf], ph, vh);
                MMA16816(acc[vf], pl, vh);
                MMA16816(acc[vf], ph, vl);
            }
        }
    }

    // ---- diagonal extra logit (single key per row) ----
#pragma unroll
    for (int r = 0; r < 2; r++) {
        int qq = (r == 0) ? r0g : r1g;
        if (qq >= 1 && qq < GGG) {
            bool pick = (qq <= NPP);
            int nd = pick ? (NPP + qq) : (qq - NPP);
            int ppd = pick ? (qq - 1) : (qq - NPP - 1);
            const float* qg = (pick ? g_Qx[0] : g_Qx[3]) + ((size_t)hb * NPP + ppd) * DKK;
            const float* kk = g_K + ((size_t)hb * GGG + nd) * DKK;
            const float* vv = g_V + ((size_t)hb * GGG + nd) * DKK;
            float s = 0.f;
#pragma unroll
            for (int k = 0; k < DKK; k++) s = fmaf(qg[k], kk[k], s);
            s *= NORMF;
            float& m = (r == 0) ? m0 : m1;
            float& l = (r == 0) ? l0 : l1;
            float mn = fmaxf(m, s);
            float c = __expf(m - mn);
            m = mn;
            l *= c;
#pragma unroll
            for (int vf = 0; vf < 4; vf++) {
                acc[vf][2 * r] *= c;
                acc[vf][2 * r + 1] *= c;
            }
            float w = __expf(s - mn);
            if (tig == 0) l += w;
#pragma unroll
            for (int vf = 0; vf < 4; vf++) {
                acc[vf][2 * r]     = fmaf(w, vv[vf * 8 + 2 * tig], acc[vf][2 * r]);
                acc[vf][2 * r + 1] = fmaf(w, vv[vf * 8 + 2 * tig + 1], acc[vf][2 * r + 1]);
            }
        }
    }

    // ---- finalize ----
    l0 += __shfl_xor_sync(0xffffffffu, l0, 1);
    l0 += __shfl_xor_sync(0xffffffffu, l0, 2);
    l1 += __shfl_xor_sync(0xffffffffu, l1, 1);
    l1 += __shfl_xor_sync(0xffffffffu, l1, 2);
    float inv0 = 1.f / l0, inv1 = 1.f / l1;

    if (r0g < GGG) {
        float* dst = g_heads + ((size_t)(b * GGG + r0g) * HH + head) * DKK;
#pragma unroll
        for (int vf = 0; vf < 4; vf++) {
            float2 v = make_float2(acc[vf][0] * inv0, acc[vf][1] * inv0);
            *(float2*)(dst + vf * 8 + 2 * tig) = v;
        }
    }
    if (r1g < GGG) {
        float* dst = g_heads + ((size_t)(b * GGG + r1g) * HH + head) * DKK;
#pragma unroll
        for (int vf = 0; vf < 4; vf++) {
            float2 v = make_float2(acc[vf][2] * inv1, acc[vf][3] * inv1);
            *(float2*)(dst + vf * 8 + 2 * tig) = v;
        }
    }
}

// =====================================================================
// Kernel C: out = heads(8208x256) @ Wout(256x256). (unchanged)
// =====================================================================
__global__ __launch_bounds__(256) void out_kernel(const float* __restrict__ Wout,
                                                  float* __restrict__ out) {
    const int M = BBB * GGG;
    const int row0 = blockIdx.x * 64;
    const int col0 = blockIdx.y * 64;
    const int tid = threadIdx.x;
    const int rg = tid >> 4;
    const int cg = tid & 15;

    __shared__ float As[64][33];
    __shared__ float Bs[32][64];

    float acc[4][4];
#pragma unroll
    for (int i = 0; i < 4; i++)
#pragma unroll
        for (int j = 0; j < 4; j++) acc[i][j] = 0.f;

    for (int kc = 0; kc < HH * DKK; kc += 32) {
#pragma unroll
        for (int i = 0; i < 2; i++) {
            int idx = tid + i * 256;
            int r = idx >> 3;
            int d4 = idx & 7;
            int gr = row0 + r;
            int grc = (gr < M) ? gr : 0;
            const float4 v = *(const float4*)(g_heads + (size_t)grc * 256 + kc + d4 * 4);
            As[r][d4 * 4 + 0] = v.x;
            As[r][d4 * 4 + 1] = v.y;
            As[r][d4 * 4 + 2] = v.z;
            As[r][d4 * 4 + 3] = v.w;
        }
#pragma unroll
        for (int i = 0; i < 2; i++) {
            int idx = tid + i * 256;
            int d = idx >> 4;
            int c4 = idx & 15;
            const float4 v = *(const float4*)(Wout + (size_t)(kc + d) * EE + col0 + c4 * 4);
            *(float4*)&Bs[d][c4 * 4] = v;
        }
        __syncthreads();

#pragma unroll
        for (int d = 0; d < 32; d++) {
            float a[4];
#pragma unroll
            for (int i = 0; i < 4; i++) a[i] = As[rg * 4 + i][d];
            const float4 b4 = *(const float4*)&Bs[d][cg * 4];
#pragma unroll
            for (int i = 0; i < 4; i++) {
                acc[i][0] = fmaf(a[i], b4.x, acc[i][0]);
                acc[i][1] = fmaf(a[i], b4.y, acc[i][1]);
                acc[i][2] = fmaf(a[i], b4.z, acc[i][2]);
                acc[i][3] = fmaf(a[i], b4.w, acc[i][3]);
            }
        }
        __syncthreads();
    }

#pragma unroll
    for (int i = 0; i < 4; i++) {
        int gr = row0 + rg * 4 + i;
        if (gr < M) {
            float4 v = make_float4(acc[i][0], acc[i][1], acc[i][2], acc[i][3]);
            *(float4*)(out + (size_t)gr * EE + col0 + cg * 4) = v;
        }
    }
}

// =====================================================================
extern "C" void kernel_launch(void* const* d_in, const int* in_sizes, int n_in,
                              void* d_out, int out_size) {
    const float* q = (const float*)d_in[0];
    const float* h = (const float*)d_in[1];
    WPtrs WP;
    for (int i = 0; i < 9; i++) WP.w[i] = (const float*)d_in[2 + i];
    const float* Wout = (const float*)d_in[11];
    float* out = (float*)d_out;

    cudaFuncSetAttribute(attn_hmma_kernel, cudaFuncAttributeMaxDynamicSharedMemorySize, SMEM_ATTN);

    cvt_x_kernel<<<dim3((XELEMS / 8 + 255) / 256, 2), 256>>>(q, h);
    cvt_w_kernel<<<(WTELEMS + 255) / 256, 256>>>(WP);

    proj_hmma_kernel<<<dim3(65, HH, 9), 256>>>();

    cvt_kv_kernel<<<dim3(8, HH * BBB), 256>>>();

    attn_hmma_kernel<<<dim3(5, BBB, HH), 256, SMEM_ATTN>>>();

    out_kernel<<<dim3((BBB * GGG + 63) / 64, EE / 64), 256>>>(Wout, out);
}